// round 8
// baseline (speedup 1.0000x reference)
#include <cuda_runtime.h>
#include <cstdint>
#include <math.h>

#define EPSF 1e-6f
#define WARPS 8

// Padded node table: up to 131072 nodes * 2 float4 = 4 MB static scratch.
__device__ float4 g_npad[131072 * 2];

// Vectorized pad: coalesced float loads -> smem -> coalesced STG.128 writes.
__global__ __launch_bounds__(256)
void pad_nodes_kernel(const float* __restrict__ nodes, int n_nodes) {
    __shared__ float st[1792];   // 256 nodes * 7 floats
    int base = blockIdx.x * 256;
    int cnt  = n_nodes - base;
    if (cnt <= 0) return;
    if (cnt > 256) cnt = 256;
    for (int k = threadIdx.x; k < cnt * 7; k += 256)
        st[k] = nodes[(size_t)base * 7 + k];
    __syncthreads();
    int t = threadIdx.x;
    if (t < cnt) {
        const float* p = st + t * 7;
        int i = base + t;
        g_npad[i * 2 + 0] = make_float4(p[0], p[1], p[2], p[3]);
        g_npad[i * 2 + 1] = make_float4(p[4], p[5], p[6], 0.0f);
    }
}

__device__ __forceinline__ uint32_t smem_u32(const void* p) {
    return (uint32_t)__cvta_generic_to_shared(p);
}
__device__ __forceinline__ void cp16(uint32_t dst, const void* src) {
    asm volatile("cp.async.cg.shared.global [%0], [%1], 16;" :: "r"(dst), "l"(src));
}
__device__ __forceinline__ void cp_commit_wait() {
    asm volatile("cp.async.commit_group;\n\tcp.async.wait_group 0;" ::: "memory");
}

__device__ __forceinline__ float3 f3cross(float3 a, float3 b) {
    return make_float3(a.y * b.z - a.z * b.y,
                       a.z * b.x - a.x * b.z,
                       a.x * b.y - a.y * b.x);
}

__device__ __forceinline__ float3 qrot(float4 q, float3 v) {
    float3 u = make_float3(q.x, q.y, q.z);
    float3 t = f3cross(u, v);
    t.x *= 2.0f; t.y *= 2.0f; t.z *= 2.0f;
    float3 c = f3cross(u, t);
    return make_float3(v.x + q.w * t.x + c.x,
                       v.y + q.w * t.y + c.y,
                       v.z + q.w * t.z + c.z);
}

__device__ __forceinline__ float4 qmul(float4 a, float4 b) {
    return make_float4(
        a.w * b.x + a.x * b.w + a.y * b.z - a.z * b.y,
        a.w * b.y - a.x * b.z + a.y * b.w + a.z * b.x,
        a.w * b.z + a.x * b.y - a.y * b.x + a.z * b.w,
        a.w * b.w - a.x * b.x - a.y * b.y - a.z * b.z);
}

// Branchless atan2(y, x) for y >= 0. Max abs error ~1e-5 rad (budget 1e-3).
__device__ __forceinline__ float fast_atan2_pos(float y, float x) {
    float ax = fabsf(x);
    float mn = fminf(ax, y), mx = fmaxf(ax, y);
    float t  = __fdividef(mn, mx);
    float t2 = t * t;
    float p  = fmaf(t2, fmaf(t2, fmaf(t2, fmaf(t2,
                0.0208351f, -0.085133f), 0.180141f), -0.3302995f), 0.9998660f);
    float at = p * t;
    at = (y > ax)    ? (1.57079632679f - at) : at;
    at = (x < 0.0f)  ? (3.14159265359f - at) : at;
    return at;
}

// Full per-edge SE(3) relative-pose error + log map (algebraically reduced).
__device__ __forceinline__ void edge_error(
    float p0, float p1, float p2, float p3, float p4, float p5, float p6,
    float4 n1a, float4 n1b, float4 n2a, float4 n2b,
    float& r0, float& r1, float& r2, float& r3, float& r4, float& r5)
{
    float3 t1 = make_float3(n1a.x, n1a.y, n1a.z);
    float4 q1 = make_float4(n1a.w, n1b.x, n1b.y, n1b.z);
    float3 t2 = make_float3(n2a.x, n2a.y, n2a.z);
    float4 q2 = make_float4(n2a.w, n2b.x, n2b.y, n2b.z);

    // qa = conj(pose.q);  t_B = qrot(qa, t2 - tp)
    float4 qa = make_float4(-p3, -p4, -p5, p6);
    float3 d  = make_float3(t2.x - p0, t2.y - p1, t2.z - p2);
    float3 tb = qrot(qa, d);

    // q_E = (qa * q2) * conj(q1);  t_E = t_B - qrot(q_E, t1)
    float4 qb = qmul(qa, q2);
    float4 qc = make_float4(-q1.x, -q1.y, -q1.z, q1.w);
    float4 qe = qmul(qb, qc);
    float3 re = qrot(qe, t1);
    float3 te = make_float3(tb.x - re.x, tb.y - re.y, tb.z - re.z);

    // se3_log with |qe| == 1 (exact trig elimination)
    float nn2 = qe.x * qe.x + qe.y * qe.y + qe.z * qe.z;
    float nn  = sqrtf(nn2);
    float theta, scale;
    if (nn > EPSF) {
        theta = 2.0f * fast_atan2_pos(nn, qe.w);
        scale = __fdividef(theta, nn);
    } else {
        float dw = (fabsf(qe.w) > EPSF) ? qe.w : 1.0f;
        scale = __fdividef(2.0f, dw);
        theta = fabsf(scale) * nn;   // tiny
    }
    float c;
    if (theta < EPSF) {
        c = 1.0f / 12.0f;
    } else {
        c = __fdividef(1.0f, theta * theta)
          - qe.w * __fdividef(0.5f, nn * theta);
    }

    float3 phi = make_float3(qe.x * scale, qe.y * scale, qe.z * scale);
    float3 pxt  = f3cross(phi, te);
    float3 ppxt = f3cross(phi, pxt);
    r0 = te.x - 0.5f * pxt.x + c * ppxt.x;
    r1 = te.y - 0.5f * pxt.y + c * ppxt.y;
    r2 = te.z - 0.5f * pxt.z + c * ppxt.z;
    r3 = phi.x; r4 = phi.y; r5 = phi.z;
}

__global__ __launch_bounds__(256)
void pose_graph_kernel(const int* __restrict__ edges,
                       const float* __restrict__ poses,
                       float* __restrict__ out,
                       int n_edges, int n_nodes)
{
    __shared__ float4 s0[WARPS][64];    // first 16B of gathered node
    __shared__ float4 s1[WARPS][64];    // second 16B
    __shared__ float  sp[WARPS][224];   // poses in; REUSED as AoS output (192 floats)

    const int warp = threadIdx.x >> 5;
    const int lane = threadIdx.x & 31;
    const int ew0  = blockIdx.x * 256 + warp * 32;   // first edge of this warp
    const int e    = ew0 + lane;

    if (ew0 + 32 <= n_edges) {
        // ================= fast, warp-autonomous path =================
        int2 vi = __ldg((const int2*)edges + e);
        int i1 = min(max(vi.x, 0), n_nodes - 1);
        int i2 = min(max(vi.y, 0), n_nodes - 1);

        // stage poses: 56 float4 per warp, cp.async (L1-bypassing)
        const float4* P4 = (const float4*)(poses + (size_t)ew0 * 7);
        uint32_t spA = smem_u32(&sp[warp][0]);
        cp16(spA + lane * 16, P4 + lane);
        if (lane < 24) cp16(spA + (32 + lane) * 16, P4 + 32 + lane);

        // gather: 64 node-halves per warp; idx redistributed via shfl;
        // lane pairs fetch the two halves of the same node (same 128B line)
        uint32_t s0A = smem_u32(&s0[warp][0]);
        uint32_t s1A = smem_u32(&s1[warp][0]);
        const int h  = lane & 1;
        const int nl = lane >> 1;
        uint32_t dstBase = (h ? s1A : s0A);
#pragma unroll
        for (int j = 0; j < 4; j++) {
            int srcLane = ((j & 1) << 4) | nl;
            int idx = __shfl_sync(0xffffffffu, (j < 2) ? i1 : i2, srcLane);
            int n = j * 16 + nl;       // slots 0..31 = node1, 32..63 = node2
            cp16(dstBase + n * 16, &g_npad[idx * 2 + h]);
        }
        cp_commit_wait();
        __syncwarp();

        float p0 = sp[warp][lane * 7 + 0], p1 = sp[warp][lane * 7 + 1];
        float p2 = sp[warp][lane * 7 + 2], p3 = sp[warp][lane * 7 + 3];
        float p4 = sp[warp][lane * 7 + 4], p5 = sp[warp][lane * 7 + 5];
        float p6 = sp[warp][lane * 7 + 6];
        float4 n1a = s0[warp][lane],      n1b = s1[warp][lane];
        float4 n2a = s0[warp][32 + lane], n2b = s1[warp][32 + lane];

        float r0, r1, r2, r3, r4, r5;
        edge_error(p0, p1, p2, p3, p4, p5, p6, n1a, n1b, n2a, n2b,
                   r0, r1, r2, r3, r4, r5);

        // AoS staging into sp via STS.64 (pose values already consumed)
        __syncwarp();
        float2* f2 = (float2*)&sp[warp][0];   // 96 float2 = 32 edges * 6 floats AoS
        f2[lane * 3 + 0] = make_float2(r0, r1);
        f2[lane * 3 + 1] = make_float2(r2, r3);
        f2[lane * 3 + 2] = make_float2(r4, r5);
        __syncwarp();

        // contiguous LDS.128 readback + streaming STG.128: 48 float4 per warp
        float4* O4 = (float4*)(out + (size_t)ew0 * 6);
        const float4* S4 = (const float4*)&sp[warp][0];
        __stwt(&O4[lane], S4[lane]);
        if (lane < 16) __stwt(&O4[32 + lane], S4[32 + lane]);
    } else if (e < n_edges) {
        // ================= scalar tail path =================
        int2 vi = __ldg((const int2*)edges + e);
        int i1 = min(max(vi.x, 0), n_nodes - 1);
        int i2 = min(max(vi.y, 0), n_nodes - 1);
        const float* P = poses + (size_t)e * 7;
        float4 n1a = __ldg(&g_npad[i1 * 2 + 0]), n1b = __ldg(&g_npad[i1 * 2 + 1]);
        float4 n2a = __ldg(&g_npad[i2 * 2 + 0]), n2b = __ldg(&g_npad[i2 * 2 + 1]);
        float r0, r1, r2, r3, r4, r5;
        edge_error(P[0], P[1], P[2], P[3], P[4], P[5], P[6],
                   n1a, n1b, n2a, n2b, r0, r1, r2, r3, r4, r5);
        float* O = out + (size_t)e * 6;
        O[0] = r0; O[1] = r1; O[2] = r2; O[3] = r3; O[4] = r4; O[5] = r5;
    }
}

extern "C" void kernel_launch(void* const* d_in, const int* in_sizes, int n_in,
                              void* d_out, int out_size)
{
    // Identify inputs by size: nodes smallest, poses largest, edges remaining.
    int ie = 0, ip = 1, in_ = 2;
    {
        long s0 = in_sizes[0], s1 = in_sizes[1], s2 = in_sizes[2];
        in_ = (s0 <= s1 && s0 <= s2) ? 0 : (s1 <= s0 && s1 <= s2) ? 1 : 2;
        ip  = (s0 >= s1 && s0 >= s2) ? 0 : (s1 >= s0 && s1 >= s2) ? 1 : 2;
        ie  = 3 - in_ - ip;
    }

    const int*   edges = (const int*)d_in[ie];
    const float* poses = (const float*)d_in[ip];
    const float* nodes = (const float*)d_in[in_];
    float*       out   = (float*)d_out;

    int n_edges = in_sizes[ie] / 2;
    int n_nodes = in_sizes[in_] / 7;
    if (n_nodes > 131072) n_nodes = 131072;  // static scratch bound

    pad_nodes_kernel<<<(n_nodes + 255) / 256, 256>>>(nodes, n_nodes);
    int blocks = (n_edges + 255) / 256;
    pose_graph_kernel<<<blocks, 256>>>(edges, poses, out, n_edges, n_nodes);
}

// round 9
// speedup vs baseline: 1.1780x; 1.1780x over previous
#include <cuda_runtime.h>
#include <cstdint>
#include <math.h>

#define EPSF 1e-6f
#define WARPS 8

// Padded node table: up to 131072 nodes * 2 float4 = 4 MB static scratch.
__device__ float4 g_npad[131072 * 2];

// Vectorized pad: coalesced float loads -> smem -> coalesced STG.128 writes.
__global__ __launch_bounds__(256)
void pad_nodes_kernel(const float* __restrict__ nodes, int n_nodes) {
    __shared__ float st[1792];   // 256 nodes * 7 floats
    int base = blockIdx.x * 256;
    int cnt  = n_nodes - base;
    if (cnt <= 0) return;
    if (cnt > 256) cnt = 256;
    for (int k = threadIdx.x; k < cnt * 7; k += 256)
        st[k] = nodes[(size_t)base * 7 + k];
    __syncthreads();
    int t = threadIdx.x;
    if (t < cnt) {
        const float* p = st + t * 7;
        int i = base + t;
        g_npad[i * 2 + 0] = make_float4(p[0], p[1], p[2], p[3]);
        g_npad[i * 2 + 1] = make_float4(p[4], p[5], p[6], 0.0f);
    }
}

__device__ __forceinline__ float3 f3cross(float3 a, float3 b) {
    return make_float3(a.y * b.z - a.z * b.y,
                       a.z * b.x - a.x * b.z,
                       a.x * b.y - a.y * b.x);
}

__device__ __forceinline__ float3 qrot(float4 q, float3 v) {
    float3 u = make_float3(q.x, q.y, q.z);
    float3 t = f3cross(u, v);
    t.x *= 2.0f; t.y *= 2.0f; t.z *= 2.0f;
    float3 c = f3cross(u, t);
    return make_float3(v.x + q.w * t.x + c.x,
                       v.y + q.w * t.y + c.y,
                       v.z + q.w * t.z + c.z);
}

__device__ __forceinline__ float4 qmul(float4 a, float4 b) {
    return make_float4(
        a.w * b.x + a.x * b.w + a.y * b.z - a.z * b.y,
        a.w * b.y - a.x * b.z + a.y * b.w + a.z * b.x,
        a.w * b.z + a.x * b.y - a.y * b.x + a.z * b.w,
        a.w * b.w - a.x * b.x - a.y * b.y - a.z * b.z);
}

// Branchless atan2(y, x) for y >= 0. Max abs error ~1e-5 rad (budget 1e-3).
__device__ __forceinline__ float fast_atan2_pos(float y, float x) {
    float ax = fabsf(x);
    float mn = fminf(ax, y), mx = fmaxf(ax, y);
    float t  = __fdividef(mn, mx);
    float t2 = t * t;
    float p  = fmaf(t2, fmaf(t2, fmaf(t2, fmaf(t2,
                0.0208351f, -0.085133f), 0.180141f), -0.3302995f), 0.9998660f);
    float at = p * t;
    at = (y > ax)    ? (1.57079632679f - at) : at;
    at = (x < 0.0f)  ? (3.14159265359f - at) : at;
    return at;
}

// Full per-edge SE(3) relative-pose error + log map (algebraically reduced).
__device__ __forceinline__ void edge_error(
    float p0, float p1, float p2, float p3, float p4, float p5, float p6,
    float4 n1a, float4 n1b, float4 n2a, float4 n2b,
    float& r0, float& r1, float& r2, float& r3, float& r4, float& r5)
{
    float3 t1 = make_float3(n1a.x, n1a.y, n1a.z);
    float4 q1 = make_float4(n1a.w, n1b.x, n1b.y, n1b.z);
    float3 t2 = make_float3(n2a.x, n2a.y, n2a.z);
    float4 q2 = make_float4(n2a.w, n2b.x, n2b.y, n2b.z);

    // qa = conj(pose.q);  t_B = qrot(qa, t2 - tp)
    float4 qa = make_float4(-p3, -p4, -p5, p6);
    float3 d  = make_float3(t2.x - p0, t2.y - p1, t2.z - p2);
    float3 tb = qrot(qa, d);

    // q_E = (qa * q2) * conj(q1);  t_E = t_B - qrot(q_E, t1)
    float4 qb = qmul(qa, q2);
    float4 qc = make_float4(-q1.x, -q1.y, -q1.z, q1.w);
    float4 qe = qmul(qb, qc);
    float3 re = qrot(qe, t1);
    float3 te = make_float3(tb.x - re.x, tb.y - re.y, tb.z - re.z);

    // se3_log with |qe| == 1 (exact trig elimination)
    float nn2 = qe.x * qe.x + qe.y * qe.y + qe.z * qe.z;
    float nn  = sqrtf(nn2);
    float theta, scale;
    if (nn > EPSF) {
        theta = 2.0f * fast_atan2_pos(nn, qe.w);
        scale = __fdividef(theta, nn);
    } else {
        float dw = (fabsf(qe.w) > EPSF) ? qe.w : 1.0f;
        scale = __fdividef(2.0f, dw);
        theta = fabsf(scale) * nn;   // tiny
    }
    float c;
    if (theta < EPSF) {
        c = 1.0f / 12.0f;
    } else {
        c = __fdividef(1.0f, theta * theta)
          - qe.w * __fdividef(0.5f, nn * theta);
    }

    float3 phi = make_float3(qe.x * scale, qe.y * scale, qe.z * scale);
    float3 pxt  = f3cross(phi, te);
    float3 ppxt = f3cross(phi, pxt);
    r0 = te.x - 0.5f * pxt.x + c * ppxt.x;
    r1 = te.y - 0.5f * pxt.y + c * ppxt.y;
    r2 = te.z - 0.5f * pxt.z + c * ppxt.z;
    r3 = phi.x; r4 = phi.y; r5 = phi.z;
}

__global__ __launch_bounds__(256, 6)
void pose_graph_kernel(const int* __restrict__ edges,
                       const float* __restrict__ poses,
                       float* __restrict__ out,
                       int n_edges, int n_nodes)
{
    // Node halves: [half*68 + slot]; +68 float4 pad shifts odd-lane STS by
    // 16 banks -> even/odd lanes hit disjoint bank halves (conflict-free).
    __shared__ float4 sn[WARPS][136];
    __shared__ float  sp[WARPS][224];   // poses in; REUSED as AoS output (192 floats)

    const int warp = threadIdx.x >> 5;
    const int lane = threadIdx.x & 31;
    const int ew0  = blockIdx.x * 256 + warp * 32;   // first edge of this warp
    const int e    = ew0 + lane;

    if (ew0 + 32 <= n_edges) {
        // ================= fast, warp-autonomous path =================
        int2 vi = __ldg((const int2*)edges + e);
        int i1 = min(max(vi.x, 0), n_nodes - 1);
        int i2 = min(max(vi.y, 0), n_nodes - 1);

        // pose stage: warp-wide LDG.128 (not per-thread cp.async; LDGSTS
        // issue floor of 8cyc/op was the R8 bottleneck)
        const float4* P4 = (const float4*)(poses + (size_t)ew0 * 7);
        float4 pa = __ldg(P4 + lane);
        float4 pb = make_float4(0.f, 0.f, 0.f, 0.f);
        if (lane < 24) pb = __ldg(P4 + 32 + lane);

        // cooperative gather: lane pairs fetch the two 16B halves of one node
        // (same 128B line) -> 16 lines per LDG.128, 4 instructions total
        const int h  = lane & 1;
        const int nl = lane >> 1;
        int idx0 = __shfl_sync(0xffffffffu, i1, nl);
        int idx1 = __shfl_sync(0xffffffffu, i1, 16 | nl);
        int idx2 = __shfl_sync(0xffffffffu, i2, nl);
        int idx3 = __shfl_sync(0xffffffffu, i2, 16 | nl);
        float4 g0 = __ldg(&g_npad[idx0 * 2 + h]);
        float4 g1 = __ldg(&g_npad[idx1 * 2 + h]);
        float4 g2 = __ldg(&g_npad[idx2 * 2 + h]);
        float4 g3 = __ldg(&g_npad[idx3 * 2 + h]);

        // redistribute through smem (STS.128, conflict-free by layout)
        ((float4*)&sp[warp][0])[lane] = pa;
        if (lane < 24) ((float4*)&sp[warp][0])[32 + lane] = pb;
        const int hb = h * 68;
        sn[warp][hb +  0 + nl] = g0;   // node1 slots  0..15
        sn[warp][hb + 16 + nl] = g1;   // node1 slots 16..31
        sn[warp][hb + 32 + nl] = g2;   // node2 slots  0..15
        sn[warp][hb + 48 + nl] = g3;   // node2 slots 16..31
        __syncwarp();

        float p0 = sp[warp][lane * 7 + 0], p1 = sp[warp][lane * 7 + 1];
        float p2 = sp[warp][lane * 7 + 2], p3 = sp[warp][lane * 7 + 3];
        float p4 = sp[warp][lane * 7 + 4], p5 = sp[warp][lane * 7 + 5];
        float p6 = sp[warp][lane * 7 + 6];
        float4 n1a = sn[warp][lane],      n1b = sn[warp][68 + lane];
        float4 n2a = sn[warp][32 + lane], n2b = sn[warp][68 + 32 + lane];

        float r0, r1, r2, r3, r4, r5;
        edge_error(p0, p1, p2, p3, p4, p5, p6, n1a, n1b, n2a, n2b,
                   r0, r1, r2, r3, r4, r5);

        // AoS staging into sp via STS.64 (pose values already consumed)
        __syncwarp();
        float2* f2 = (float2*)&sp[warp][0];   // 96 float2 = 32 edges * 6 floats AoS
        f2[lane * 3 + 0] = make_float2(r0, r1);
        f2[lane * 3 + 1] = make_float2(r2, r3);
        f2[lane * 3 + 2] = make_float2(r4, r5);
        __syncwarp();

        // contiguous LDS.128 readback + streaming STG.128: 48 float4 per warp
        float4* O4 = (float4*)(out + (size_t)ew0 * 6);
        const float4* S4 = (const float4*)&sp[warp][0];
        __stwt(&O4[lane], S4[lane]);
        if (lane < 16) __stwt(&O4[32 + lane], S4[32 + lane]);
    } else if (e < n_edges) {
        // ================= scalar tail path =================
        int2 vi = __ldg((const int2*)edges + e);
        int i1 = min(max(vi.x, 0), n_nodes - 1);
        int i2 = min(max(vi.y, 0), n_nodes - 1);
        const float* P = poses + (size_t)e * 7;
        float4 n1a = __ldg(&g_npad[i1 * 2 + 0]), n1b = __ldg(&g_npad[i1 * 2 + 1]);
        float4 n2a = __ldg(&g_npad[i2 * 2 + 0]), n2b = __ldg(&g_npad[i2 * 2 + 1]);
        float r0, r1, r2, r3, r4, r5;
        edge_error(P[0], P[1], P[2], P[3], P[4], P[5], P[6],
                   n1a, n1b, n2a, n2b, r0, r1, r2, r3, r4, r5);
        float* O = out + (size_t)e * 6;
        O[0] = r0; O[1] = r1; O[2] = r2; O[3] = r3; O[4] = r4; O[5] = r5;
    }
}

extern "C" void kernel_launch(void* const* d_in, const int* in_sizes, int n_in,
                              void* d_out, int out_size)
{
    // Identify inputs by size: nodes smallest, poses largest, edges remaining.
    int ie = 0, ip = 1, in_ = 2;
    {
        long s0 = in_sizes[0], s1 = in_sizes[1], s2 = in_sizes[2];
        in_ = (s0 <= s1 && s0 <= s2) ? 0 : (s1 <= s0 && s1 <= s2) ? 1 : 2;
        ip  = (s0 >= s1 && s0 >= s2) ? 0 : (s1 >= s0 && s1 >= s2) ? 1 : 2;
        ie  = 3 - in_ - ip;
    }

    const int*   edges = (const int*)d_in[ie];
    const float* poses = (const float*)d_in[ip];
    const float* nodes = (const float*)d_in[in_];
    float*       out   = (float*)d_out;

    int n_edges = in_sizes[ie] / 2;
    int n_nodes = in_sizes[in_] / 7;
    if (n_nodes > 131072) n_nodes = 131072;  // static scratch bound

    pad_nodes_kernel<<<(n_nodes + 255) / 256, 256>>>(nodes, n_nodes);
    int blocks = (n_edges + 255) / 256;
    pose_graph_kernel<<<blocks, 256>>>(edges, poses, out, n_edges, n_nodes);
}

// round 10
// speedup vs baseline: 1.3042x; 1.1071x over previous
#include <cuda_runtime.h>
#include <cstdint>
#include <math.h>

#define EPSF 1e-6f
#define WARPS 8

// Padded node table: up to 131072 nodes * 2 float4 = 4 MB static scratch.
__device__ float4 g_npad[131072 * 2];

// Vectorized pad: coalesced float loads -> smem -> coalesced STG.128 writes.
__global__ __launch_bounds__(256)
void pad_nodes_kernel(const float* __restrict__ nodes, int n_nodes) {
    __shared__ float st[1792];   // 256 nodes * 7 floats
    int base = blockIdx.x * 256;
    int cnt  = n_nodes - base;
    if (cnt <= 0) return;
    if (cnt > 256) cnt = 256;
    for (int k = threadIdx.x; k < cnt * 7; k += 256)
        st[k] = nodes[(size_t)base * 7 + k];
    __syncthreads();
    int t = threadIdx.x;
    if (t < cnt) {
        const float* p = st + t * 7;
        int i = base + t;
        g_npad[i * 2 + 0] = make_float4(p[0], p[1], p[2], p[3]);
        g_npad[i * 2 + 1] = make_float4(p[4], p[5], p[6], 0.0f);
    }
}

__device__ __forceinline__ float3 f3cross(float3 a, float3 b) {
    return make_float3(a.y * b.z - a.z * b.y,
                       a.z * b.x - a.x * b.z,
                       a.x * b.y - a.y * b.x);
}

__device__ __forceinline__ float3 qrot(float4 q, float3 v) {
    float3 u = make_float3(q.x, q.y, q.z);
    float3 t = f3cross(u, v);
    t.x *= 2.0f; t.y *= 2.0f; t.z *= 2.0f;
    float3 c = f3cross(u, t);
    return make_float3(v.x + q.w * t.x + c.x,
                       v.y + q.w * t.y + c.y,
                       v.z + q.w * t.z + c.z);
}

__device__ __forceinline__ float4 qmul(float4 a, float4 b) {
    return make_float4(
        a.w * b.x + a.x * b.w + a.y * b.z - a.z * b.y,
        a.w * b.y - a.x * b.z + a.y * b.w + a.z * b.x,
        a.w * b.z + a.x * b.y - a.y * b.x + a.z * b.w,
        a.w * b.w - a.x * b.x - a.y * b.y - a.z * b.z);
}

// Branchless atan2(y, x) for y >= 0. Max abs error ~1e-5 rad (budget 1e-3).
__device__ __forceinline__ float fast_atan2_pos(float y, float x) {
    float ax = fabsf(x);
    float mn = fminf(ax, y), mx = fmaxf(ax, y);
    float t  = __fdividef(mn, mx);
    float t2 = t * t;
    float p  = fmaf(t2, fmaf(t2, fmaf(t2, fmaf(t2,
                0.0208351f, -0.085133f), 0.180141f), -0.3302995f), 0.9998660f);
    float at = p * t;
    at = (y > ax)    ? (1.57079632679f - at) : at;
    at = (x < 0.0f)  ? (3.14159265359f - at) : at;
    return at;
}

// Full per-edge SE(3) relative-pose error + log map (algebraically reduced).
__device__ __forceinline__ void edge_error(
    float p0, float p1, float p2, float p3, float p4, float p5, float p6,
    float4 n1a, float4 n1b, float4 n2a, float4 n2b,
    float& r0, float& r1, float& r2, float& r3, float& r4, float& r5)
{
    float3 t1 = make_float3(n1a.x, n1a.y, n1a.z);
    float4 q1 = make_float4(n1a.w, n1b.x, n1b.y, n1b.z);
    float3 t2 = make_float3(n2a.x, n2a.y, n2a.z);
    float4 q2 = make_float4(n2a.w, n2b.x, n2b.y, n2b.z);

    // qa = conj(pose.q);  t_B = qrot(qa, t2 - tp)
    float4 qa = make_float4(-p3, -p4, -p5, p6);
    float3 d  = make_float3(t2.x - p0, t2.y - p1, t2.z - p2);
    float3 tb = qrot(qa, d);

    // q_E = (qa * q2) * conj(q1);  t_E = t_B - qrot(q_E, t1)
    float4 qb = qmul(qa, q2);
    float4 qc = make_float4(-q1.x, -q1.y, -q1.z, q1.w);
    float4 qe = qmul(qb, qc);
    float3 re = qrot(qe, t1);
    float3 te = make_float3(tb.x - re.x, tb.y - re.y, tb.z - re.z);

    // se3_log with |qe| == 1 (exact trig elimination)
    float nn2 = qe.x * qe.x + qe.y * qe.y + qe.z * qe.z;
    float nn  = sqrtf(nn2);
    float theta, scale;
    if (nn > EPSF) {
        theta = 2.0f * fast_atan2_pos(nn, qe.w);
        scale = __fdividef(theta, nn);
    } else {
        float dw = (fabsf(qe.w) > EPSF) ? qe.w : 1.0f;
        scale = __fdividef(2.0f, dw);
        theta = fabsf(scale) * nn;   // tiny
    }
    float c;
    if (theta < EPSF) {
        c = 1.0f / 12.0f;
    } else {
        c = __fdividef(1.0f, theta * theta)
          - qe.w * __fdividef(0.5f, nn * theta);
    }

    float3 phi = make_float3(qe.x * scale, qe.y * scale, qe.z * scale);
    float3 pxt  = f3cross(phi, te);
    float3 ppxt = f3cross(phi, pxt);
    r0 = te.x - 0.5f * pxt.x + c * ppxt.x;
    r1 = te.y - 0.5f * pxt.y + c * ppxt.y;
    r2 = te.z - 0.5f * pxt.z + c * ppxt.z;
    r3 = phi.x; r4 = phi.y; r5 = phi.z;
}

__device__ __forceinline__ float4 shflx1(float4 v) {
    float4 r;
    r.x = __shfl_xor_sync(0xffffffffu, v.x, 1);
    r.y = __shfl_xor_sync(0xffffffffu, v.y, 1);
    r.z = __shfl_xor_sync(0xffffffffu, v.z, 1);
    r.w = __shfl_xor_sync(0xffffffffu, v.w, 1);
    return r;
}
__device__ __forceinline__ float4 sel4(bool c, float4 a, float4 b) {
    return make_float4(c ? a.x : b.x, c ? a.y : b.y,
                       c ? a.z : b.z, c ? a.w : b.w);
}

__global__ __launch_bounds__(256)
void pose_graph_kernel(const int* __restrict__ edges,
                       const float* __restrict__ poses,
                       float* __restrict__ out,
                       int n_edges, int n_nodes)
{
    __shared__ float sp[WARPS][224];   // poses in; REUSED as AoS output (192 floats)

    const int warp = threadIdx.x >> 5;
    const int lane = threadIdx.x & 31;
    const int ew0  = blockIdx.x * 256 + warp * 32;   // first edge of this warp
    const int e    = ew0 + lane;

    if (ew0 + 32 <= n_edges) {
        // ================= fast, warp-autonomous path =================
        int2 vi = __ldg((const int2*)edges + e);
        int i1 = min(max(vi.x, 0), n_nodes - 1);
        int i2 = min(max(vi.y, 0), n_nodes - 1);

        // pose stage: warp-wide LDG.128 -> STS.128
        const float4* P4 = (const float4*)(poses + (size_t)ew0 * 7);
        float4 pa = __ldg(P4 + lane);
        ((float4*)&sp[warp][0])[lane] = pa;
        if (lane < 24) {
            float4 pb = __ldg(P4 + 32 + lane);
            ((float4*)&sp[warp][0])[32 + lane] = pb;
        }

        // cooperative gather: lane pairs fetch the two 16B halves of one node
        // (same 128B line) -> 16 lines per LDG.128, 4 instructions total
        const int h  = lane & 1;
        const int nl = lane >> 1;
        int idx0 = __shfl_sync(0xffffffffu, i1, nl);        // node1, slots  0..15
        int idx1 = __shfl_sync(0xffffffffu, i1, 16 | nl);   // node1, slots 16..31
        int idx2 = __shfl_sync(0xffffffffu, i2, nl);        // node2, slots  0..15
        int idx3 = __shfl_sync(0xffffffffu, i2, 16 | nl);   // node2, slots 16..31
        float4 g0 = __ldg(&g_npad[idx0 * 2 + h]);
        float4 g1 = __ldg(&g_npad[idx1 * 2 + h]);
        float4 g2 = __ldg(&g_npad[idx2 * 2 + h]);
        float4 g3 = __ldg(&g_npad[idx3 * 2 + h]);

        // butterfly exchange with pre-selected operand: the consumer of this
        // lane pair's data IS the pair itself. Lane l computes edge
        // m = 16*(l&1) + (l>>1); even lane needs partner's g0 (half1 of its
        // node1) and sends its g1 (half0 of partner's node1) — one shfl_xor
        // per component serves both directions. Zero smem for node data.
        float4 recv1 = shflx1(sel4(h == 0, g1, g0));
        float4 recv2 = shflx1(sel4(h == 0, g3, g2));
        float4 n1a = sel4(h == 0, g0, recv1);   // half0: t0 t1 t2 q0
        float4 n1b = sel4(h == 0, recv1, g1);   // half1: q1 q2 q3 --
        float4 n2a = sel4(h == 0, g2, recv2);
        float4 n2b = sel4(h == 0, recv2, g3);

        const int m = (h << 4) | nl;   // permuted edge slot this lane computes
        __syncwarp();                  // pose STS visible warp-wide

        float p0 = sp[warp][m * 7 + 0], p1 = sp[warp][m * 7 + 1];
        float p2 = sp[warp][m * 7 + 2], p3 = sp[warp][m * 7 + 3];
        float p4 = sp[warp][m * 7 + 4], p5 = sp[warp][m * 7 + 5];
        float p6 = sp[warp][m * 7 + 6];

        float r0, r1, r2, r3, r4, r5;
        edge_error(p0, p1, p2, p3, p4, p5, p6, n1a, n1b, n2a, n2b,
                   r0, r1, r2, r3, r4, r5);

        // AoS staging into sp via STS.64 (pose values already consumed)
        __syncwarp();
        float2* f2 = (float2*)&sp[warp][0];   // 96 float2 = 32 edges * 6 floats AoS
        f2[m * 3 + 0] = make_float2(r0, r1);
        f2[m * 3 + 1] = make_float2(r2, r3);
        f2[m * 3 + 2] = make_float2(r4, r5);
        __syncwarp();

        // contiguous LDS.128 readback + streaming STG.128: 48 float4 per warp
        float4* O4 = (float4*)(out + (size_t)ew0 * 6);
        const float4* S4 = (const float4*)&sp[warp][0];
        __stwt(&O4[lane], S4[lane]);
        if (lane < 16) __stwt(&O4[32 + lane], S4[32 + lane]);
    } else if (e < n_edges) {
        // ================= scalar tail path =================
        int2 vi = __ldg((const int2*)edges + e);
        int i1 = min(max(vi.x, 0), n_nodes - 1);
        int i2 = min(max(vi.y, 0), n_nodes - 1);
        const float* P = poses + (size_t)e * 7;
        float4 n1a = __ldg(&g_npad[i1 * 2 + 0]), n1b = __ldg(&g_npad[i1 * 2 + 1]);
        float4 n2a = __ldg(&g_npad[i2 * 2 + 0]), n2b = __ldg(&g_npad[i2 * 2 + 1]);
        float r0, r1, r2, r3, r4, r5;
        edge_error(P[0], P[1], P[2], P[3], P[4], P[5], P[6],
                   n1a, n1b, n2a, n2b, r0, r1, r2, r3, r4, r5);
        float* O = out + (size_t)e * 6;
        O[0] = r0; O[1] = r1; O[2] = r2; O[3] = r3; O[4] = r4; O[5] = r5;
    }
}

extern "C" void kernel_launch(void* const* d_in, const int* in_sizes, int n_in,
                              void* d_out, int out_size)
{
    // Identify inputs by size: nodes smallest, poses largest, edges remaining.
    int ie = 0, ip = 1, in_ = 2;
    {
        long s0 = in_sizes[0], s1 = in_sizes[1], s2 = in_sizes[2];
        in_ = (s0 <= s1 && s0 <= s2) ? 0 : (s1 <= s0 && s1 <= s2) ? 1 : 2;
        ip  = (s0 >= s1 && s0 >= s2) ? 0 : (s1 >= s0 && s1 >= s2) ? 1 : 2;
        ie  = 3 - in_ - ip;
    }

    const int*   edges = (const int*)d_in[ie];
    const float* poses = (const float*)d_in[ip];
    const float* nodes = (const float*)d_in[in_];
    float*       out   = (float*)d_out;

    int n_edges = in_sizes[ie] / 2;
    int n_nodes = in_sizes[in_] / 7;
    if (n_nodes > 131072) n_nodes = 131072;  // static scratch bound

    pad_nodes_kernel<<<(n_nodes + 255) / 256, 256>>>(nodes, n_nodes);
    int blocks = (n_edges + 255) / 256;
    pose_graph_kernel<<<blocks, 256>>>(edges, poses, out, n_edges, n_nodes);
}